// round 4
// baseline (speedup 1.0000x reference)
#include <cuda_runtime.h>
#include <stdint.h>

#define NN 50000
#define DD 64
#define DV4 16
#define EMAX 800000

// Scratch (device globals -- referenced ONLY inside device code)
__device__ float g_tmpA[NN * DD];   // h2 (post-gemm)
__device__ float g_tmpB[NN * DD];   // h1' (layer-0 output pre-scaled for layer 1)
__device__ float g_invO[NN];
__device__ float g_invI[NN];
__device__ int   g_degO[NN];
__device__ int   g_degI[NN];
__device__ int   g_rowptr[NN + 1];
__device__ int   g_cur[NN];
__device__ unsigned g_csr[EMAX];    // src | (ef&1)<<31

// ---------------------------------------------------------------------------
__global__ void k_init() {
    int i = blockIdx.x * blockDim.x + threadIdx.x;
    if (i < NN) { g_degO[i] = 0; g_degI[i] = 0; }
}

// degrees: 4 edges/thread, int4 loads, fire-and-forget reds (no return -> REDG)
__global__ void k_degree(const int* __restrict__ src, const int* __restrict__ dst, int E) {
    int t = blockIdx.x * blockDim.x + threadIdx.x;
    int base = t * 4;
    if (base + 3 < E) {
        int4 s = *reinterpret_cast<const int4*>(src + base);
        int4 d = *reinterpret_cast<const int4*>(dst + base);
        atomicAdd(&g_degO[s.x], 1); atomicAdd(&g_degO[s.y], 1);
        atomicAdd(&g_degO[s.z], 1); atomicAdd(&g_degO[s.w], 1);
        atomicAdd(&g_degI[d.x], 1); atomicAdd(&g_degI[d.y], 1);
        atomicAdd(&g_degI[d.z], 1); atomicAdd(&g_degI[d.w], 1);
    } else {
        for (int e = base; e < E; e++) {
            atomicAdd(&g_degO[src[e]], 1);
            atomicAdd(&g_degI[dst[e]], 1);
        }
    }
}

// exclusive prefix sum of in-degrees -> rowptr/cur; also invO/invI (single block)
__global__ void k_scan() {
    __shared__ int warpsum[32];
    __shared__ int s_carry;
    int t = threadIdx.x, lane = t & 31, w = t >> 5;
    if (t == 0) s_carry = 0;
    __syncthreads();
    for (int base = 0; base < NN; base += 1024) {
        int i = base + t;
        int v = (i < NN) ? g_degI[i] : 0;
        int x = v;
#pragma unroll
        for (int o = 1; o < 32; o <<= 1) {
            int y = __shfl_up_sync(0xFFFFFFFFu, x, o);
            if (lane >= o) x += y;
        }
        if (lane == 31) warpsum[w] = x;
        __syncthreads();
        if (w == 0) {
            int s = warpsum[lane];
#pragma unroll
            for (int o = 1; o < 32; o <<= 1) {
                int y = __shfl_up_sync(0xFFFFFFFFu, s, o);
                if (lane >= o) s += y;
            }
            warpsum[lane] = s;
        }
        __syncthreads();
        int woff = (w > 0) ? warpsum[w - 1] : 0;
        int excl = x - v + woff + s_carry;
        if (i < NN) {
            g_rowptr[i] = excl;
            g_cur[i] = excl;
            g_invI[i] = rsqrtf(fmaxf((float)v, 1.0f));
            g_invO[i] = rsqrtf(fmaxf((float)g_degO[i], 1.0f));
        }
        __syncthreads();
        if (t == 0) s_carry += warpsum[31];
        __syncthreads();
    }
    if (t == 0) g_rowptr[NN] = s_carry;
}

// bin edges into CSR-by-dst: 4 edges/thread for atomic MLP
__global__ void k_bin(const int* __restrict__ src, const int* __restrict__ dst,
                      const int* __restrict__ ef, int E) {
    int t = blockIdx.x * blockDim.x + threadIdx.x;
    int base = t * 4;
    if (base + 3 < E) {
        int4 s = *reinterpret_cast<const int4*>(src + base);
        int4 d = *reinterpret_cast<const int4*>(dst + base);
        int4 f = *reinterpret_cast<const int4*>(ef + base);
        int p0 = atomicAdd(&g_cur[d.x], 1);
        int p1 = atomicAdd(&g_cur[d.y], 1);
        int p2 = atomicAdd(&g_cur[d.z], 1);
        int p3 = atomicAdd(&g_cur[d.w], 1);
        g_csr[p0] = (unsigned)s.x | ((unsigned)(f.x & 1) << 31);
        g_csr[p1] = (unsigned)s.y | ((unsigned)(f.y & 1) << 31);
        g_csr[p2] = (unsigned)s.z | ((unsigned)(f.z & 1) << 31);
        g_csr[p3] = (unsigned)s.w | ((unsigned)(f.w & 1) << 31);
    } else {
        for (int e = base; e < E; e++) {
            int pos = atomicAdd(&g_cur[dst[e]], 1);
            g_csr[pos] = (unsigned)src[e] | ((unsigned)(ef[e] & 1) << 31);
        }
    }
}

// ---------------------------------------------------------------------------
// pull0: tmpB[d] = invI[d]*invO[d] * sum_e invO[s]*x[s]   (h1', layer-1-ready)
__global__ void k_pull0(const float4* __restrict__ x4) {
    int gid = blockIdx.x * blockDim.x + threadIdx.x;
    int node = gid >> 5;
    if (node >= NN) return;
    int lane = gid & 31, col = lane & 15, half = lane >> 4;
    int beg = g_rowptr[node], end = g_rowptr[node + 1];

    float4 acc = make_float4(0.f, 0.f, 0.f, 0.f);
    int j = beg + half;
    for (; j + 6 < end; j += 8) {
        unsigned v0 = g_csr[j], v1 = g_csr[j + 2], v2 = g_csr[j + 4], v3 = g_csr[j + 6];
        int s0 = v0 & 0x7FFFFFFF, s1 = v1 & 0x7FFFFFFF, s2 = v2 & 0x7FFFFFFF, s3 = v3 & 0x7FFFFFFF;
        float w0 = g_invO[s0], w1 = g_invO[s1], w2 = g_invO[s2], w3 = g_invO[s3];
        float4 a0 = x4[(size_t)s0 * DV4 + col];
        float4 a1 = x4[(size_t)s1 * DV4 + col];
        float4 a2 = x4[(size_t)s2 * DV4 + col];
        float4 a3 = x4[(size_t)s3 * DV4 + col];
        acc.x += a0.x*w0 + a1.x*w1 + a2.x*w2 + a3.x*w3;
        acc.y += a0.y*w0 + a1.y*w1 + a2.y*w2 + a3.y*w3;
        acc.z += a0.z*w0 + a1.z*w1 + a2.z*w2 + a3.z*w3;
        acc.w += a0.w*w0 + a1.w*w1 + a2.w*w2 + a3.w*w3;
    }
    for (; j < end; j += 2) {
        unsigned v = g_csr[j];
        int s = v & 0x7FFFFFFF;
        float wv = g_invO[s];
        float4 a = x4[(size_t)s * DV4 + col];
        acc.x += a.x * wv; acc.y += a.y * wv; acc.z += a.z * wv; acc.w += a.w * wv;
    }
    acc.x += __shfl_xor_sync(0xFFFFFFFFu, acc.x, 16);
    acc.y += __shfl_xor_sync(0xFFFFFFFFu, acc.y, 16);
    acc.z += __shfl_xor_sync(0xFFFFFFFFu, acc.z, 16);
    acc.w += __shfl_xor_sync(0xFFFFFFFFu, acc.w, 16);
    if (half == 0) {
        float sc = g_invI[node] * g_invO[node];
        acc.x *= sc; acc.y *= sc; acc.z *= sc; acc.w *= sc;
        reinterpret_cast<float4*>(g_tmpB)[node * DV4 + col] = acc;
    }
}

// pull1 + gemm fused: tmpA[d] = (invI[d] * sum tmpB[s]) @ W + b
__global__ __launch_bounds__(1024) void k_pull1g(const float* __restrict__ W,
                                                 const float* __restrict__ b) {
    __shared__ float2 Ws[DD * 32];            // W as float2 pairs: Ws[k*32+p] = W[k][2p..2p+1]
    __shared__ float  bs[DD];
    __shared__ float  rowbuf[32][DD];

    for (int i = threadIdx.x; i < DD * 32; i += 1024)
        Ws[i] = reinterpret_cast<const float2*>(W)[i];
    if (threadIdx.x < DD) bs[threadIdx.x] = b[threadIdx.x];
    __syncthreads();

    int w = threadIdx.x >> 5, lane = threadIdx.x & 31;
    int node = blockIdx.x * 32 + w;
    if (node >= NN) return;
    int col = lane & 15, half = lane >> 4;
    int beg = g_rowptr[node], end = g_rowptr[node + 1];
    const float4* srcb = reinterpret_cast<const float4*>(g_tmpB);

    float4 acc = make_float4(0.f, 0.f, 0.f, 0.f);
    int j = beg + half;
    for (; j + 6 < end; j += 8) {
        unsigned v0 = g_csr[j], v1 = g_csr[j + 2], v2 = g_csr[j + 4], v3 = g_csr[j + 6];
        float4 a0 = srcb[(size_t)(v0 & 0x7FFFFFFFu) * DV4 + col];
        float4 a1 = srcb[(size_t)(v1 & 0x7FFFFFFFu) * DV4 + col];
        float4 a2 = srcb[(size_t)(v2 & 0x7FFFFFFFu) * DV4 + col];
        float4 a3 = srcb[(size_t)(v3 & 0x7FFFFFFFu) * DV4 + col];
        acc.x += a0.x + a1.x + a2.x + a3.x;
        acc.y += a0.y + a1.y + a2.y + a3.y;
        acc.z += a0.z + a1.z + a2.z + a3.z;
        acc.w += a0.w + a1.w + a2.w + a3.w;
    }
    for (; j < end; j += 2) {
        unsigned v = g_csr[j];
        float4 a = srcb[(size_t)(v & 0x7FFFFFFFu) * DV4 + col];
        acc.x += a.x; acc.y += a.y; acc.z += a.z; acc.w += a.w;
    }
    acc.x += __shfl_xor_sync(0xFFFFFFFFu, acc.x, 16);
    acc.y += __shfl_xor_sync(0xFFFFFFFFu, acc.y, 16);
    acc.z += __shfl_xor_sync(0xFFFFFFFFu, acc.z, 16);
    acc.w += __shfl_xor_sync(0xFFFFFFFFu, acc.w, 16);

    if (half == 0) {
        float ii = g_invI[node];
        acc.x *= ii; acc.y *= ii; acc.z *= ii; acc.w *= ii;
        *reinterpret_cast<float4*>(&rowbuf[w][col * 4]) = acc;
    }
    __syncwarp();

    // gemm: lane owns output columns (2*lane, 2*lane+1)
    float o0 = bs[2 * lane], o1 = bs[2 * lane + 1];
#pragma unroll
    for (int k = 0; k < DD; k++) {
        float xv = rowbuf[w][k];          // smem broadcast
        float2 ww = Ws[k * 32 + lane];    // conflict-free 64-bit LDS
        o0 += xv * ww.x;
        o1 += xv * ww.y;
    }
    reinterpret_cast<float2*>(g_tmpA)[node * 32 + lane] = make_float2(o0, o1);
}

// pull2: out[d] = sum coef_e * tmpA[s]
__global__ void k_pull2(float4* __restrict__ outbuf) {
    int gid = blockIdx.x * blockDim.x + threadIdx.x;
    int node = gid >> 5;
    if (node >= NN) return;
    int lane = gid & 31, col = lane & 15, half = lane >> 4;
    int beg = g_rowptr[node], end = g_rowptr[node + 1];
    const float4* srcb = reinterpret_cast<const float4*>(g_tmpA);

    float4 acc = make_float4(0.f, 0.f, 0.f, 0.f);
    int j = beg + half;
    for (; j + 6 < end; j += 8) {
        unsigned v0 = g_csr[j], v1 = g_csr[j + 2], v2 = g_csr[j + 4], v3 = g_csr[j + 6];
        float4 a0 = srcb[(size_t)(v0 & 0x7FFFFFFFu) * DV4 + col];
        float4 a1 = srcb[(size_t)(v1 & 0x7FFFFFFFu) * DV4 + col];
        float4 a2 = srcb[(size_t)(v2 & 0x7FFFFFFFu) * DV4 + col];
        float4 a3 = srcb[(size_t)(v3 & 0x7FFFFFFFu) * DV4 + col];
        float c0 = (v0 >> 31) ? 1.f : 2.f, c1 = (v1 >> 31) ? 1.f : 2.f;
        float c2 = (v2 >> 31) ? 1.f : 2.f, c3 = (v3 >> 31) ? 1.f : 2.f;
        acc.x += a0.x*c0 + a1.x*c1 + a2.x*c2 + a3.x*c3;
        acc.y += a0.y*c0 + a1.y*c1 + a2.y*c2 + a3.y*c3;
        acc.z += a0.z*c0 + a1.z*c1 + a2.z*c2 + a3.z*c3;
        acc.w += a0.w*c0 + a1.w*c1 + a2.w*c2 + a3.w*c3;
    }
    for (; j < end; j += 2) {
        unsigned v = g_csr[j];
        float4 a = srcb[(size_t)(v & 0x7FFFFFFFu) * DV4 + col];
        float c = (v >> 31) ? 1.f : 2.f;
        acc.x += a.x * c; acc.y += a.y * c; acc.z += a.z * c; acc.w += a.w * c;
    }
    acc.x += __shfl_xor_sync(0xFFFFFFFFu, acc.x, 16);
    acc.y += __shfl_xor_sync(0xFFFFFFFFu, acc.y, 16);
    acc.z += __shfl_xor_sync(0xFFFFFFFFu, acc.z, 16);
    acc.w += __shfl_xor_sync(0xFFFFFFFFu, acc.w, 16);
    if (half == 0)
        outbuf[node * DV4 + col] = acc;
}

extern "C" void kernel_launch(void* const* d_in, const int* in_sizes, int n_in,
                              void* d_out, int out_size) {
    const float4* x4  = (const float4*)d_in[0];
    const float*  W   = (const float*)d_in[1];
    const float*  b   = (const float*)d_in[2];
    const int*    src = (const int*)d_in[3];
    const int*    dst = (const int*)d_in[4];
    const int*    ef  = (const int*)d_in[5];
    float4* out = (float4*)d_out;

    const int E = in_sizes[3];
    const int TB = 256;
    int gNode = (NN + TB - 1) / TB;
    int gE4   = ((E + 3) / 4 + TB - 1) / TB;
    int gWarp = (NN * 32 + TB - 1) / TB;
    int gP1   = (NN + 31) / 32;

    k_init<<<gNode, TB>>>();
    k_degree<<<gE4, TB>>>(src, dst, E);
    k_scan<<<1, 1024>>>();
    k_bin<<<gE4, TB>>>(src, dst, ef, E);
    k_pull0<<<gWarp, TB>>>(x4);
    k_pull1g<<<gP1, 1024>>>(W, b);
    k_pull2<<<gWarp, TB>>>(out);
}

// round 5
// speedup vs baseline: 1.0793x; 1.0793x over previous
#include <cuda_runtime.h>
#include <stdint.h>

#define NN 50000
#define DD 64
#define DV4 16
#define EMAX 800000

// Scratch (device globals -- referenced ONLY inside device code)
__device__ float g_tmpA[NN * DD];
__device__ float g_tmpB[NN * DD];
__device__ float g_invO[NN];
__device__ float g_invI[NN];
__device__ int   g_degO[NN];
__device__ int   g_degI[NN];
__device__ int   g_rowptr[NN + 1];
__device__ int   g_cur[NN];
__device__ unsigned g_csr[EMAX];    // src | (ef&1)<<31

// ---------------------------------------------------------------------------
__global__ void k_init() {
    int i = blockIdx.x * blockDim.x + threadIdx.x;
    if (i * 4 + 3 < NN) {
        *reinterpret_cast<int4*>(g_degO + i * 4) = make_int4(0, 0, 0, 0);
        *reinterpret_cast<int4*>(g_degI + i * 4) = make_int4(0, 0, 0, 0);
    }
}

// degrees: 1 edge/thread (R3 config -- measured faster than 4x batching)
__global__ void k_degree(const int* __restrict__ src, const int* __restrict__ dst, int E) {
    int e = blockIdx.x * blockDim.x + threadIdx.x;
    if (e < E) {
        atomicAdd(&g_degO[src[e]], 1);
        atomicAdd(&g_degI[dst[e]], 1);
    }
}

// exclusive prefix sum of in-degrees -> rowptr/cur; also invI/invO.
// int4-vectorized: 4096 nodes per block-iteration (13 iters for 50k).
__global__ void k_scan() {
    __shared__ int warpsum[32];
    __shared__ int s_carry;
    int t = threadIdx.x, lane = t & 31, w = t >> 5;
    if (t == 0) s_carry = 0;
    __syncthreads();
    for (int base = 0; base < NN; base += 4096) {
        int i = base + t * 4;                 // first node of this thread's quad
        int4 v = (i < NN) ? *reinterpret_cast<const int4*>(g_degI + i)
                          : make_int4(0, 0, 0, 0);
        int tsum = v.x + v.y + v.z + v.w;
        int x = tsum;
#pragma unroll
        for (int o = 1; o < 32; o <<= 1) {
            int y = __shfl_up_sync(0xFFFFFFFFu, x, o);
            if (lane >= o) x += y;
        }
        if (lane == 31) warpsum[w] = x;
        __syncthreads();
        if (w == 0) {
            int s = warpsum[lane];
#pragma unroll
            for (int o = 1; o < 32; o <<= 1) {
                int y = __shfl_up_sync(0xFFFFFFFFu, s, o);
                if (lane >= o) s += y;
            }
            warpsum[lane] = s;
        }
        __syncthreads();
        int woff = (w > 0) ? warpsum[w - 1] : 0;
        int e0 = x - tsum + woff + s_carry;   // exclusive at first elem
        if (i < NN) {
            int e1 = e0 + v.x, e2 = e1 + v.y, e3 = e2 + v.z;
            *reinterpret_cast<int4*>(g_rowptr + i) = make_int4(e0, e1, e2, e3);
            *reinterpret_cast<int4*>(g_cur + i)    = make_int4(e0, e1, e2, e3);
            int4 dO = *reinterpret_cast<const int4*>(g_degO + i);
            g_invI[i]     = rsqrtf(fmaxf((float)v.x, 1.0f));
            g_invI[i + 1] = rsqrtf(fmaxf((float)v.y, 1.0f));
            g_invI[i + 2] = rsqrtf(fmaxf((float)v.z, 1.0f));
            g_invI[i + 3] = rsqrtf(fmaxf((float)v.w, 1.0f));
            g_invO[i]     = rsqrtf(fmaxf((float)dO.x, 1.0f));
            g_invO[i + 1] = rsqrtf(fmaxf((float)dO.y, 1.0f));
            g_invO[i + 2] = rsqrtf(fmaxf((float)dO.z, 1.0f));
            g_invO[i + 3] = rsqrtf(fmaxf((float)dO.w, 1.0f));
        }
        __syncthreads();
        if (t == 0) s_carry += warpsum[31];
        __syncthreads();
    }
    if (t == 0) g_rowptr[NN] = s_carry;
}

// bin edges into CSR-by-dst (1 edge/thread; R3 config)
__global__ void k_bin(const int* __restrict__ src, const int* __restrict__ dst,
                      const int* __restrict__ ef, int E) {
    int e = blockIdx.x * blockDim.x + threadIdx.x;
    if (e >= E) return;
    int d = dst[e];
    int pos = atomicAdd(&g_cur[d], 1);
    g_csr[pos] = (unsigned)src[e] | ((unsigned)(ef[e] & 1) << 31);
}

// tmpA = x * invO (invO precomputed in k_scan)
__global__ void k_scale_x(const float4* __restrict__ x4) {
    int tid = blockIdx.x * blockDim.x + threadIdx.x;
    if (tid >= NN * DV4) return;
    int n = tid >> 4;
    float io = g_invO[n];
    float4 v = x4[tid];
    v.x *= io; v.y *= io; v.z *= io; v.w *= io;
    reinterpret_cast<float4*>(g_tmpA)[tid] = v;
}

// ---------------------------------------------------------------------------
// Pull aggregation, one warp per dst node, 16 lanes = 16 float4 cols, two
// half-warps split edges. Fully-predicated unroll-4 body: every iteration
// keeps 4 independent feature gathers in flight (no serial remainder tail).
// MODE 0: tmpB[d] = (sum tmpA[s]) * invI[d]*invO[d]
// MODE 1: tmpA[d] = (sum tmpB[s]) * invI[d]
// MODE 2: out[d]  =  sum coef_e * tmpB[s]
template <int MODE>
__global__ void k_pull(float4* __restrict__ outbuf) {
    int gid = blockIdx.x * blockDim.x + threadIdx.x;
    int node = gid >> 5;
    if (node >= NN) return;
    int lane = gid & 31, col = lane & 15, half = lane >> 4;
    const float4* srcb = reinterpret_cast<const float4*>(MODE == 0 ? g_tmpA : g_tmpB);
    int beg = g_rowptr[node], end = g_rowptr[node + 1];

    float4 acc = make_float4(0.f, 0.f, 0.f, 0.f);
    for (int j = beg + half; j < end; j += 8) {
        int last = end - 1;
        int j1 = j + 2 <= last ? j + 2 : last;
        int j2 = j + 4 <= last ? j + 4 : last;
        int j3 = j + 6 <= last ? j + 6 : last;
        unsigned v0 = g_csr[j],  v1 = g_csr[j1];
        unsigned v2 = g_csr[j2], v3 = g_csr[j3];
        float4 a0 = srcb[(size_t)(v0 & 0x7FFFFFFFu) * DV4 + col];
        float4 a1 = srcb[(size_t)(v1 & 0x7FFFFFFFu) * DV4 + col];
        float4 a2 = srcb[(size_t)(v2 & 0x7FFFFFFFu) * DV4 + col];
        float4 a3 = srcb[(size_t)(v3 & 0x7FFFFFFFu) * DV4 + col];
        float c0, c1, c2, c3;
        if (MODE == 2) {
            c0 = (float)(2 - (int)(v0 >> 31));
            c1 = (j + 2 < end) ? (float)(2 - (int)(v1 >> 31)) : 0.f;
            c2 = (j + 4 < end) ? (float)(2 - (int)(v2 >> 31)) : 0.f;
            c3 = (j + 6 < end) ? (float)(2 - (int)(v3 >> 31)) : 0.f;
        } else {
            c0 = 1.f;
            c1 = (j + 2 < end) ? 1.f : 0.f;
            c2 = (j + 4 < end) ? 1.f : 0.f;
            c3 = (j + 6 < end) ? 1.f : 0.f;
        }
        acc.x += a0.x*c0 + a1.x*c1 + a2.x*c2 + a3.x*c3;
        acc.y += a0.y*c0 + a1.y*c1 + a2.y*c2 + a3.y*c3;
        acc.z += a0.z*c0 + a1.z*c1 + a2.z*c2 + a3.z*c3;
        acc.w += a0.w*c0 + a1.w*c1 + a2.w*c2 + a3.w*c3;
    }
    acc.x += __shfl_xor_sync(0xFFFFFFFFu, acc.x, 16);
    acc.y += __shfl_xor_sync(0xFFFFFFFFu, acc.y, 16);
    acc.z += __shfl_xor_sync(0xFFFFFFFFu, acc.z, 16);
    acc.w += __shfl_xor_sync(0xFFFFFFFFu, acc.w, 16);

    if (half == 0) {
        float sc = 1.f;
        if (MODE == 0) sc = g_invI[node] * g_invO[node];
        if (MODE == 1) sc = g_invI[node];
        acc.x *= sc; acc.y *= sc; acc.z *= sc; acc.w *= sc;
        if (MODE == 0)
            reinterpret_cast<float4*>(g_tmpB)[node * DV4 + col] = acc;
        else if (MODE == 1)
            reinterpret_cast<float4*>(g_tmpA)[node * DV4 + col] = acc;
        else
            outbuf[node * DV4 + col] = acc;
    }
}

// tmpB = tmpA @ W + b   (invI folded into tmpA by pull<1>)
__global__ void k_gemm(const float* __restrict__ W, const float* __restrict__ b) {
    __shared__ float Ws[DD * DD];
    __shared__ float bs[DD];
    for (int i = threadIdx.x; i < DD * DD; i += blockDim.x) Ws[i] = W[i];
    if (threadIdx.x < DD) bs[threadIdx.x] = b[threadIdx.x];
    __syncthreads();

    int tid = blockIdx.x * blockDim.x + threadIdx.x;
    if (tid >= NN * DV4) return;
    int n = tid >> 4;
    int jq = (tid & 15) * 4;
    const float* row = g_tmpA + n * DD;
    float4 a = make_float4(bs[jq], bs[jq + 1], bs[jq + 2], bs[jq + 3]);
#pragma unroll
    for (int k = 0; k < DD; k++) {
        float xv = row[k];
        float4 w = *reinterpret_cast<const float4*>(Ws + k * DD + jq);
        a.x += xv * w.x; a.y += xv * w.y; a.z += xv * w.z; a.w += xv * w.w;
    }
    reinterpret_cast<float4*>(g_tmpB)[tid] = a;
}

extern "C" void kernel_launch(void* const* d_in, const int* in_sizes, int n_in,
                              void* d_out, int out_size) {
    const float4* x4  = (const float4*)d_in[0];
    const float*  W   = (const float*)d_in[1];
    const float*  b   = (const float*)d_in[2];
    const int*    src = (const int*)d_in[3];
    const int*    dst = (const int*)d_in[4];
    const int*    ef  = (const int*)d_in[5];
    float4* out = (float4*)d_out;

    const int E = in_sizes[3];
    const int TB = 256;
    int gInit = ((NN + 3) / 4 + TB - 1) / TB;
    int gE    = (E + TB - 1) / TB;
    int gN16  = (NN * DV4 + TB - 1) / TB;
    int gWarp = (NN * 32 + TB - 1) / TB;

    k_init<<<gInit, TB>>>();
    k_degree<<<gE, TB>>>(src, dst, E);
    k_scan<<<1, 1024>>>();
    k_bin<<<gE, TB>>>(src, dst, ef, E);
    k_scale_x<<<gN16, TB>>>(x4);
    k_pull<0><<<gWarp, TB>>>(nullptr);
    k_pull<1><<<gWarp, TB>>>(nullptr);
    k_gemm<<<gN16, TB>>>(W, b);
    k_pull<2><<<gWarp, TB>>>(out);
}

// round 6
// speedup vs baseline: 1.1547x; 1.0698x over previous
#include <cuda_runtime.h>
#include <stdint.h>

#define NN 50000
#define DD 64
#define DV4 16
#define EMAX 800000

// Scratch (device globals -- referenced ONLY inside device code)
__device__ float g_tmpA[NN * DD];
__device__ float g_tmpB[NN * DD];
__device__ float g_invO[NN];
__device__ float g_invI[NN];
__device__ int   g_deg[2 * NN];      // [0,NN) = degO, [NN,2NN) = degI
__device__ int   g_rowptr[NN];       // excl prefix after scan; becomes rowptr[d+1] after bin
__device__ unsigned g_csr[EMAX];     // src | (ef&1)<<31

__device__ __forceinline__ uint64_t pack2(float a, float b) {
    uint64_t r;
    asm("mov.b64 %0, {%1, %2};" : "=l"(r) : "f"(a), "f"(b));
    return r;
}
__device__ __forceinline__ void unpack2(uint64_t v, float& a, float& b) {
    asm("mov.b64 {%0, %1}, %2;" : "=f"(a), "=f"(b) : "l"(v));
}
__device__ __forceinline__ void fma2(uint64_t& acc, uint64_t x, uint64_t w) {
    asm("fma.rn.f32x2 %0, %1, %2, %0;" : "+l"(acc) : "l"(x), "l"(w));
}

// ---------------------------------------------------------------------------
// degrees: 1 edge/thread (measured best config)
__global__ void k_degree(const int* __restrict__ src, const int* __restrict__ dst, int E) {
    int e = blockIdx.x * blockDim.x + threadIdx.x;
    if (e < E) {
        atomicAdd(&g_deg[src[e]], 1);         // degO
        atomicAdd(&g_deg[NN + dst[e]], 1);    // degI
    }
}

// exclusive prefix sum of in-degrees -> rowptr; also invI/invO.
// int4-vectorized: 4096 nodes per block-iteration.
__global__ void k_scan() {
    __shared__ int warpsum[32];
    __shared__ int s_carry;
    int t = threadIdx.x, lane = t & 31, w = t >> 5;
    if (t == 0) s_carry = 0;
    __syncthreads();
    for (int base = 0; base < NN; base += 4096) {
        int i = base + t * 4;
        int4 v = (i < NN) ? *reinterpret_cast<const int4*>(g_deg + NN + i)
                          : make_int4(0, 0, 0, 0);
        int tsum = v.x + v.y + v.z + v.w;
        int x = tsum;
#pragma unroll
        for (int o = 1; o < 32; o <<= 1) {
            int y = __shfl_up_sync(0xFFFFFFFFu, x, o);
            if (lane >= o) x += y;
        }
        if (lane == 31) warpsum[w] = x;
        __syncthreads();
        if (w == 0) {
            int s = warpsum[lane];
#pragma unroll
            for (int o = 1; o < 32; o <<= 1) {
                int y = __shfl_up_sync(0xFFFFFFFFu, s, o);
                if (lane >= o) s += y;
            }
            warpsum[lane] = s;
        }
        __syncthreads();
        int woff = (w > 0) ? warpsum[w - 1] : 0;
        int e0 = x - tsum + woff + s_carry;
        if (i < NN) {
            int e1 = e0 + v.x, e2 = e1 + v.y, e3 = e2 + v.z;
            *reinterpret_cast<int4*>(g_rowptr + i) = make_int4(e0, e1, e2, e3);
            int4 dO = *reinterpret_cast<const int4*>(g_deg + i);
            g_invI[i]     = rsqrtf(fmaxf((float)v.x, 1.0f));
            g_invI[i + 1] = rsqrtf(fmaxf((float)v.y, 1.0f));
            g_invI[i + 2] = rsqrtf(fmaxf((float)v.z, 1.0f));
            g_invI[i + 3] = rsqrtf(fmaxf((float)v.w, 1.0f));
            g_invO[i]     = rsqrtf(fmaxf((float)dO.x, 1.0f));
            g_invO[i + 1] = rsqrtf(fmaxf((float)dO.y, 1.0f));
            g_invO[i + 2] = rsqrtf(fmaxf((float)dO.z, 1.0f));
            g_invO[i + 3] = rsqrtf(fmaxf((float)dO.w, 1.0f));
        }
        __syncthreads();
        if (t == 0) s_carry += warpsum[31];
        __syncthreads();
    }
}

// bin edges into CSR-by-dst, bumping g_rowptr in place (2 edges/thread).
// After this kernel, g_rowptr[d] == exclusive_prefix[d+1].
__global__ void k_bin(const int* __restrict__ src, const int* __restrict__ dst,
                      const int* __restrict__ ef, int E) {
    int t = blockIdx.x * blockDim.x + threadIdx.x;
    int base = t * 2;
    if (base + 1 < E) {
        int2 s = *reinterpret_cast<const int2*>(src + base);
        int2 d = *reinterpret_cast<const int2*>(dst + base);
        int2 f = *reinterpret_cast<const int2*>(ef + base);
        int p0 = atomicAdd(&g_rowptr[d.x], 1);
        int p1 = atomicAdd(&g_rowptr[d.y], 1);
        g_csr[p0] = (unsigned)s.x | ((unsigned)(f.x & 1) << 31);
        g_csr[p1] = (unsigned)s.y | ((unsigned)(f.y & 1) << 31);
    } else if (base < E) {
        int pos = atomicAdd(&g_rowptr[dst[base]], 1);
        g_csr[pos] = (unsigned)src[base] | ((unsigned)(ef[base] & 1) << 31);
    }
}

// tmpA = x * invO
__global__ void k_scale_x(const float4* __restrict__ x4) {
    int tid = blockIdx.x * blockDim.x + threadIdx.x;
    if (tid >= NN * DV4) return;
    int n = tid >> 4;
    float io = g_invO[n];
    float4 v = x4[tid];
    v.x *= io; v.y *= io; v.z *= io; v.w *= io;
    reinterpret_cast<float4*>(g_tmpA)[tid] = v;
}

// ---------------------------------------------------------------------------
// Pull aggregation (R3 body): one warp per dst node, 16 lanes = 16 float4
// cols, two half-warps split edges, unroll-4 main loop + short remainder.
// MODE 0: tmpB[d] = (sum tmpA[s]) * invI[d]*invO[d]
// MODE 1: tmpA[d] = (sum tmpB[s]) * invI[d]
// MODE 2: out[d]  =  sum coef_e * tmpB[s]
template <int MODE>
__global__ void k_pull(float4* __restrict__ outbuf) {
    int gid = blockIdx.x * blockDim.x + threadIdx.x;
    int node = gid >> 5;
    if (node >= NN) return;
    int lane = gid & 31, col = lane & 15, half = lane >> 4;
    const float4* srcb = reinterpret_cast<const float4*>(MODE == 0 ? g_tmpA : g_tmpB);
    int beg = node ? g_rowptr[node - 1] : 0;
    int end = g_rowptr[node];

    float4 acc = make_float4(0.f, 0.f, 0.f, 0.f);
    int j = beg + half;
    for (; j + 6 < end; j += 8) {
        unsigned v0 = g_csr[j], v1 = g_csr[j + 2], v2 = g_csr[j + 4], v3 = g_csr[j + 6];
        float4 a0 = srcb[(size_t)(v0 & 0x7FFFFFFFu) * DV4 + col];
        float4 a1 = srcb[(size_t)(v1 & 0x7FFFFFFFu) * DV4 + col];
        float4 a2 = srcb[(size_t)(v2 & 0x7FFFFFFFu) * DV4 + col];
        float4 a3 = srcb[(size_t)(v3 & 0x7FFFFFFFu) * DV4 + col];
        if (MODE == 2) {
            float c0 = (v0 >> 31) ? 1.f : 2.f, c1 = (v1 >> 31) ? 1.f : 2.f;
            float c2 = (v2 >> 31) ? 1.f : 2.f, c3 = (v3 >> 31) ? 1.f : 2.f;
            acc.x += a0.x*c0 + a1.x*c1 + a2.x*c2 + a3.x*c3;
            acc.y += a0.y*c0 + a1.y*c1 + a2.y*c2 + a3.y*c3;
            acc.z += a0.z*c0 + a1.z*c1 + a2.z*c2 + a3.z*c3;
            acc.w += a0.w*c0 + a1.w*c1 + a2.w*c2 + a3.w*c3;
        } else {
            acc.x += a0.x + a1.x + a2.x + a3.x;
            acc.y += a0.y + a1.y + a2.y + a3.y;
            acc.z += a0.z + a1.z + a2.z + a3.z;
            acc.w += a0.w + a1.w + a2.w + a3.w;
        }
    }
    for (; j < end; j += 2) {
        unsigned v = g_csr[j];
        float4 a = srcb[(size_t)(v & 0x7FFFFFFFu) * DV4 + col];
        float c = (MODE == 2) ? ((v >> 31) ? 1.f : 2.f) : 1.f;
        acc.x += a.x * c; acc.y += a.y * c; acc.z += a.z * c; acc.w += a.w * c;
    }
    acc.x += __shfl_xor_sync(0xFFFFFFFFu, acc.x, 16);
    acc.y += __shfl_xor_sync(0xFFFFFFFFu, acc.y, 16);
    acc.z += __shfl_xor_sync(0xFFFFFFFFu, acc.z, 16);
    acc.w += __shfl_xor_sync(0xFFFFFFFFu, acc.w, 16);

    if (half == 0) {
        float sc = 1.f;
        if (MODE == 0) sc = g_invI[node] * g_invO[node];
        if (MODE == 1) sc = g_invI[node];
        acc.x *= sc; acc.y *= sc; acc.z *= sc; acc.w *= sc;
        if (MODE == 0)
            reinterpret_cast<float4*>(g_tmpB)[node * DV4 + col] = acc;
        else if (MODE == 1)
            reinterpret_cast<float4*>(g_tmpA)[node * DV4 + col] = acc;
        else
            outbuf[node * DV4 + col] = acc;
    }
}

// tmpB = tmpA @ W + b   (packed f32x2 FMA; invI folded into tmpA by pull<1>)
__global__ void k_gemm(const float* __restrict__ W, const float* __restrict__ b) {
    __shared__ float Ws[DD * DD];
    __shared__ float bs[DD];
    for (int i = threadIdx.x; i < DD * DD; i += blockDim.x) Ws[i] = W[i];
    if (threadIdx.x < DD) bs[threadIdx.x] = b[threadIdx.x];
    __syncthreads();

    int tid = blockIdx.x * blockDim.x + threadIdx.x;
    if (tid >= NN * DV4) return;
    int n = tid >> 4;
    int jq = (tid & 15) * 4;
    const float4* row4 = reinterpret_cast<const float4*>(g_tmpA + n * DD);

    uint64_t acc0 = pack2(bs[jq],     bs[jq + 1]);
    uint64_t acc1 = pack2(bs[jq + 2], bs[jq + 3]);
#pragma unroll
    for (int k4 = 0; k4 < DD / 4; k4++) {
        float4 xv = row4[k4];
#pragma unroll
        for (int c = 0; c < 4; c++) {
            float xc = (c == 0) ? xv.x : (c == 1) ? xv.y : (c == 2) ? xv.z : xv.w;
            uint64_t x2 = pack2(xc, xc);
            ulonglong2 w2 = *reinterpret_cast<const ulonglong2*>(Ws + (k4 * 4 + c) * DD + jq);
            fma2(acc0, x2, w2.x);
            fma2(acc1, x2, w2.y);
        }
    }
    float4 o;
    unpack2(acc0, o.x, o.y);
    unpack2(acc1, o.z, o.w);
    reinterpret_cast<float4*>(g_tmpB)[tid] = o;
}

extern "C" void kernel_launch(void* const* d_in, const int* in_sizes, int n_in,
                              void* d_out, int out_size) {
    const float4* x4  = (const float4*)d_in[0];
    const float*  W   = (const float*)d_in[1];
    const float*  b   = (const float*)d_in[2];
    const int*    src = (const int*)d_in[3];
    const int*    dst = (const int*)d_in[4];
    const int*    ef  = (const int*)d_in[5];
    float4* out = (float4*)d_out;

    const int E = in_sizes[3];
    const int TB = 256;
    int gE    = (E + TB - 1) / TB;
    int gE2   = ((E + 1) / 2 + TB - 1) / TB;
    int gN16  = (NN * DV4 + TB - 1) / TB;
    int gWarp = (NN * 32 + TB - 1) / TB;

    void* degPtr = nullptr;
    cudaGetSymbolAddress(&degPtr, g_deg);
    cudaMemsetAsync(degPtr, 0, 2 * NN * sizeof(int));

    k_degree<<<gE, TB>>>(src, dst, E);
    k_scan<<<1, 1024>>>();
    k_bin<<<gE2, TB>>>(src, dst, ef, E);
    k_scale_x<<<gN16, TB>>>(x4);
    k_pull<0><<<gWarp, TB>>>(nullptr);
    k_pull<1><<<gWarp, TB>>>(nullptr);
    k_gemm<<<gN16, TB>>>(W, b);
    k_pull<2><<<gWarp, TB>>>(out);
}

// round 7
// speedup vs baseline: 1.1672x; 1.0108x over previous
#include <cuda_runtime.h>
#include <cuda_fp16.h>
#include <stdint.h>

#define NN 50000
#define DD 64
#define DV4 16
#define EMAX 800000

// Scratch (device globals -- referenced ONLY inside device code)
__device__ __align__(256) __half g_hA[NN * DD];   // x * invO          (fp16)
__device__ __align__(256) __half g_hB[NN * DD];   // h1' (layer-1-ready, fp16)
__device__ __align__(256) __half g_hC[NN * DD];   // h2 (post-gemm,     fp16)
__device__ float g_tmpF[NN * DD];                 // pull1 out (fp32, streamed into gemm)
__device__ float g_invO[NN];
__device__ float g_invI[NN];
__device__ int   g_deg[2 * NN];      // [0,NN) = degO, [NN,2NN) = degI
__device__ int   g_rowptr[NN];       // excl prefix after scan; rowptr[d+1] after bin
__device__ unsigned g_csr[EMAX];     // src | (ef&1)<<31

__device__ __forceinline__ uint64_t pack2(float a, float b) {
    uint64_t r; asm("mov.b64 %0, {%1, %2};" : "=l"(r) : "f"(a), "f"(b)); return r;
}
__device__ __forceinline__ void unpack2(uint64_t v, float& a, float& b) {
    asm("mov.b64 {%0, %1}, %2;" : "=f"(a), "=f"(b) : "l"(v));
}
__device__ __forceinline__ void fma2(uint64_t& acc, uint64_t x, uint64_t w) {
    asm("fma.rn.f32x2 %0, %1, %2, %0;" : "+l"(acc) : "l"(x), "l"(w));
}

// gather 4 halves (8B) of row s, col group c, accumulate *coef into acc
__device__ __forceinline__ void acc_h4(const __half* base, unsigned v, int col,
                                       float coef, float4& acc) {
    size_t s = (size_t)(v & 0x7FFFFFFFu);
    uint2 r = *reinterpret_cast<const uint2*>(base + s * DD + col * 4);
    __half2 h0 = *reinterpret_cast<const __half2*>(&r.x);
    __half2 h1 = *reinterpret_cast<const __half2*>(&r.y);
    float2 f0 = __half22float2(h0);
    float2 f1 = __half22float2(h1);
    acc.x += f0.x * coef; acc.y += f0.y * coef;
    acc.z += f1.x * coef; acc.w += f1.y * coef;
}

// ---------------------------------------------------------------------------
// degrees: 1 edge/thread
__global__ void k_degree(const int* __restrict__ src, const int* __restrict__ dst, int E) {
    int e = blockIdx.x * blockDim.x + threadIdx.x;
    if (e < E) {
        atomicAdd(&g_deg[src[e]], 1);
        atomicAdd(&g_deg[NN + dst[e]], 1);
    }
}

// exclusive prefix sum of in-degrees -> rowptr; also invI/invO (int4-vectorized)
__global__ void k_scan() {
    __shared__ int warpsum[32];
    __shared__ int s_carry;
    int t = threadIdx.x, lane = t & 31, w = t >> 5;
    if (t == 0) s_carry = 0;
    __syncthreads();
    for (int base = 0; base < NN; base += 4096) {
        int i = base + t * 4;
        int4 v = (i < NN) ? *reinterpret_cast<const int4*>(g_deg + NN + i)
                          : make_int4(0, 0, 0, 0);
        int tsum = v.x + v.y + v.z + v.w;
        int x = tsum;
#pragma unroll
        for (int o = 1; o < 32; o <<= 1) {
            int y = __shfl_up_sync(0xFFFFFFFFu, x, o);
            if (lane >= o) x += y;
        }
        if (lane == 31) warpsum[w] = x;
        __syncthreads();
        if (w == 0) {
            int s = warpsum[lane];
#pragma unroll
            for (int o = 1; o < 32; o <<= 1) {
                int y = __shfl_up_sync(0xFFFFFFFFu, s, o);
                if (lane >= o) s += y;
            }
            warpsum[lane] = s;
        }
        __syncthreads();
        int woff = (w > 0) ? warpsum[w - 1] : 0;
        int e0 = x - tsum + woff + s_carry;
        if (i < NN) {
            int e1 = e0 + v.x, e2 = e1 + v.y, e3 = e2 + v.z;
            *reinterpret_cast<int4*>(g_rowptr + i) = make_int4(e0, e1, e2, e3);
            int4 dO = *reinterpret_cast<const int4*>(g_deg + i);
            g_invI[i]     = rsqrtf(fmaxf((float)v.x, 1.0f));
            g_invI[i + 1] = rsqrtf(fmaxf((float)v.y, 1.0f));
            g_invI[i + 2] = rsqrtf(fmaxf((float)v.z, 1.0f));
            g_invI[i + 3] = rsqrtf(fmaxf((float)v.w, 1.0f));
            g_invO[i]     = rsqrtf(fmaxf((float)dO.x, 1.0f));
            g_invO[i + 1] = rsqrtf(fmaxf((float)dO.y, 1.0f));
            g_invO[i + 2] = rsqrtf(fmaxf((float)dO.z, 1.0f));
            g_invO[i + 3] = rsqrtf(fmaxf((float)dO.w, 1.0f));
        }
        __syncthreads();
        if (t == 0) s_carry += warpsum[31];
        __syncthreads();
    }
}

// bin edges into CSR-by-dst, bumping g_rowptr in place (2 edges/thread)
__global__ void k_bin(const int* __restrict__ src, const int* __restrict__ dst,
                      const int* __restrict__ ef, int E) {
    int t = blockIdx.x * blockDim.x + threadIdx.x;
    int base = t * 2;
    if (base + 1 < E) {
        int2 s = *reinterpret_cast<const int2*>(src + base);
        int2 d = *reinterpret_cast<const int2*>(dst + base);
        int2 f = *reinterpret_cast<const int2*>(ef + base);
        int p0 = atomicAdd(&g_rowptr[d.x], 1);
        int p1 = atomicAdd(&g_rowptr[d.y], 1);
        g_csr[p0] = (unsigned)s.x | ((unsigned)(f.x & 1) << 31);
        g_csr[p1] = (unsigned)s.y | ((unsigned)(f.y & 1) << 31);
    } else if (base < E) {
        int pos = atomicAdd(&g_rowptr[dst[base]], 1);
        g_csr[pos] = (unsigned)src[base] | ((unsigned)(ef[base] & 1) << 31);
    }
}

// hA = fp16(x * invO)
__global__ void k_scale_x(const float4* __restrict__ x4) {
    int tid = blockIdx.x * blockDim.x + threadIdx.x;
    if (tid >= NN * DV4) return;
    int n = tid >> 4, c = tid & 15;
    float io = g_invO[n];
    float4 v = x4[tid];
    __half2 h0 = __floats2half2_rn(v.x * io, v.y * io);
    __half2 h1 = __floats2half2_rn(v.z * io, v.w * io);
    uint2 st;
    st.x = *reinterpret_cast<const unsigned*>(&h0);
    st.y = *reinterpret_cast<const unsigned*>(&h1);
    *reinterpret_cast<uint2*>(g_hA + (size_t)n * DD + c * 4) = st;
}

// ---------------------------------------------------------------------------
// Pull aggregation over fp16 rows (128B/row = 1 cache line). One warp per dst
// node; 16 lanes = 16 half4 col groups; two half-warps split edges.
// MODE 0: hB[d]   = fp16( (sum hA[s]) * invI[d]*invO[d] )
// MODE 1: tmpF[d] =       (sum hB[s]) * invI[d]            (fp32, for gemm)
// MODE 2: out[d]  =        sum coef_e * hC[s]              (fp32)
template <int MODE>
__global__ void k_pull(float4* __restrict__ outbuf) {
    int gid = blockIdx.x * blockDim.x + threadIdx.x;
    int node = gid >> 5;
    if (node >= NN) return;
    int lane = gid & 31, col = lane & 15, half = lane >> 4;
    const __half* srcb = (MODE == 0) ? g_hA : (MODE == 1) ? g_hB : g_hC;
    int beg = node ? g_rowptr[node - 1] : 0;
    int end = g_rowptr[node];

    float4 acc = make_float4(0.f, 0.f, 0.f, 0.f);
    int j = beg + half;
    for (; j + 6 < end; j += 8) {
        unsigned v0 = g_csr[j], v1 = g_csr[j + 2], v2 = g_csr[j + 4], v3 = g_csr[j + 6];
        float c0 = 1.f, c1 = 1.f, c2 = 1.f, c3 = 1.f;
        if (MODE == 2) {
            c0 = (v0 >> 31) ? 1.f : 2.f; c1 = (v1 >> 31) ? 1.f : 2.f;
            c2 = (v2 >> 31) ? 1.f : 2.f; c3 = (v3 >> 31) ? 1.f : 2.f;
        }
        acc_h4(srcb, v0, col, c0, acc);
        acc_h4(srcb, v1, col, c1, acc);
        acc_h4(srcb, v2, col, c2, acc);
        acc_h4(srcb, v3, col, c3, acc);
    }
    for (; j < end; j += 2) {
        unsigned v = g_csr[j];
        float c = (MODE == 2) ? ((v >> 31) ? 1.f : 2.f) : 1.f;
        acc_h4(srcb, v, col, c, acc);
    }
    acc.x += __shfl_xor_sync(0xFFFFFFFFu, acc.x, 16);
    acc.y += __shfl_xor_sync(0xFFFFFFFFu, acc.y, 16);
    acc.z += __shfl_xor_sync(0xFFFFFFFFu, acc.z, 16);
    acc.w += __shfl_xor_sync(0xFFFFFFFFu, acc.w, 16);

    if (half == 0) {
        if (MODE == 0) {
            float sc = g_invI[node] * g_invO[node];
            __half2 h0 = __floats2half2_rn(acc.x * sc, acc.y * sc);
            __half2 h1 = __floats2half2_rn(acc.z * sc, acc.w * sc);
            uint2 st;
            st.x = *reinterpret_cast<const unsigned*>(&h0);
            st.y = *reinterpret_cast<const unsigned*>(&h1);
            *reinterpret_cast<uint2*>(g_hB + (size_t)node * DD + col * 4) = st;
        } else if (MODE == 1) {
            float sc = g_invI[node];
            acc.x *= sc; acc.y *= sc; acc.z *= sc; acc.w *= sc;
            reinterpret_cast<float4*>(g_tmpF)[node * DV4 + col] = acc;
        } else {
            outbuf[node * DV4 + col] = acc;
        }
    }
}

// hC = fp16( tmpF @ W + b )   (packed f32x2 FMA, W in smem)
__global__ void k_gemm(const float* __restrict__ W, const float* __restrict__ b) {
    __shared__ float Ws[DD * DD];
    __shared__ float bs[DD];
    for (int i = threadIdx.x; i < DD * DD; i += blockDim.x) Ws[i] = W[i];
    if (threadIdx.x < DD) bs[threadIdx.x] = b[threadIdx.x];
    __syncthreads();

    int tid = blockIdx.x * blockDim.x + threadIdx.x;
    if (tid >= NN * DV4) return;
    int n = tid >> 4;
    int jq = (tid & 15) * 4;
    const float4* row4 = reinterpret_cast<const float4*>(g_tmpF + (size_t)n * DD);

    uint64_t acc0 = pack2(bs[jq],     bs[jq + 1]);
    uint64_t acc1 = pack2(bs[jq + 2], bs[jq + 3]);
#pragma unroll
    for (int k4 = 0; k4 < DD / 4; k4++) {
        float4 xv = row4[k4];
#pragma unroll
        for (int c = 0; c < 4; c++) {
            float xc = (c == 0) ? xv.x : (c == 1) ? xv.y : (c == 2) ? xv.z : xv.w;
            uint64_t x2 = pack2(xc, xc);
            ulonglong2 w2 = *reinterpret_cast<const ulonglong2*>(Ws + (k4 * 4 + c) * DD + jq);
            fma2(acc0, x2, w2.x);
            fma2(acc1, x2, w2.y);
        }
    }
    float o0, o1, o2, o3;
    unpack2(acc0, o0, o1);
    unpack2(acc1, o2, o3);
    __half2 h0 = __floats2half2_rn(o0, o1);
    __half2 h1 = __floats2half2_rn(o2, o3);
    uint2 st;
    st.x = *reinterpret_cast<const unsigned*>(&h0);
    st.y = *reinterpret_cast<const unsigned*>(&h1);
    *reinterpret_cast<uint2*>(g_hC + (size_t)n * DD + jq) = st;
}

extern "C" void kernel_launch(void* const* d_in, const int* in_sizes, int n_in,
                              void* d_out, int out_size) {
    const float4* x4  = (const float4*)d_in[0];
    const float*  W   = (const float*)d_in[1];
    const float*  b   = (const float*)d_in[2];
    const int*    src = (const int*)d_in[3];
    const int*    dst = (const int*)d_in[4];
    const int*    ef  = (const int*)d_in[5];
    float4* out = (float4*)d_out;

    const int E = in_sizes[3];
    const int TB = 256;
    int gE    = (E + TB - 1) / TB;
    int gE2   = ((E + 1) / 2 + TB - 1) / TB;
    int gN16  = (NN * DV4 + TB - 1) / TB;
    int gWarp = (NN * 32 + TB - 1) / TB;

    void* degPtr = nullptr;
    cudaGetSymbolAddress(&degPtr, g_deg);
    cudaMemsetAsync(degPtr, 0, 2 * NN * sizeof(int));

    k_degree<<<gE, TB>>>(src, dst, E);
    k_scan<<<1, 1024>>>();
    k_bin<<<gE2, TB>>>(src, dst, ef, E);
    k_scale_x<<<gN16, TB>>>(x4);
    k_pull<0><<<gWarp, TB>>>(nullptr);
    k_pull<1><<<gWarp, TB>>>(nullptr);
    k_gemm<<<gN16, TB>>>(W, b);
    k_pull<2><<<gWarp, TB>>>(out);
}

// round 8
// speedup vs baseline: 1.5529x; 1.3305x over previous
#include <cuda_runtime.h>
#include <cuda_fp16.h>
#include <stdint.h>

#define NN 50000
#define DD 64
#define DV4 16
#define EMAX 800000
#define SCAN_B 196              // scan blocks: 196*256 = 50176 >= NN

// Scratch (device globals -- referenced ONLY inside device code)
__device__ __align__(256) __half g_hA[NN * DD];   // x * invO
__device__ __align__(256) __half g_hB[NN * DD];   // h1'
__device__ __align__(256) __half g_hY[NN * DD];   // invI * agg(h1')  (gemm input)
__device__ __align__(256) __half g_hC[NN * DD];   // h2 (post-gemm)
__device__ int g_deg[2 * NN];        // [0,NN)=degO (filled by bin), [NN,2NN)=degI
__device__ int g_rowptr[NN];         // excl prefix; becomes rowptr[d+1] after bin
__device__ int g_part[SCAN_B];       // scan phase-1 partials
__device__ int g_poff[SCAN_B];       // scan phase-2 exclusive offsets
__device__ unsigned g_csr[EMAX];     // src | (ef&1)<<31

__device__ __forceinline__ uint64_t pack2(float a, float b) {
    uint64_t r; asm("mov.b64 %0, {%1, %2};" : "=l"(r) : "f"(a), "f"(b)); return r;
}
__device__ __forceinline__ void unpack2(uint64_t v, float& a, float& b) {
    asm("mov.b64 {%0, %1}, %2;" : "=f"(a), "=f"(b) : "l"(v));
}
__device__ __forceinline__ void fma2(uint64_t& acc, uint64_t x, uint64_t w) {
    asm("fma.rn.f32x2 %0, %1, %2, %0;" : "+l"(acc) : "l"(x), "l"(w));
}
__device__ __forceinline__ void acc_h4(const __half* base, unsigned v, int col,
                                       float coef, float4& acc) {
    size_t s = (size_t)(v & 0x7FFFFFFFu);
    uint2 r = *reinterpret_cast<const uint2*>(base + s * DD + col * 4);
    float2 f0 = __half22float2(*reinterpret_cast<const __half2*>(&r.x));
    float2 f1 = __half22float2(*reinterpret_cast<const __half2*>(&r.y));
    acc.x += f0.x * coef; acc.y += f0.y * coef;
    acc.z += f1.x * coef; acc.w += f1.y * coef;
}
__device__ __forceinline__ void store_h4(__half* base, size_t n, int col, float4 v) {
    __half2 h0 = __floats2half2_rn(v.x, v.y);
    __half2 h1 = __floats2half2_rn(v.z, v.w);
    uint2 st;
    st.x = *reinterpret_cast<const unsigned*>(&h0);
    st.y = *reinterpret_cast<const unsigned*>(&h1);
    *reinterpret_cast<uint2*>(base + n * DD + col * 4) = st;
}

// ---------------------------------------------------------------------------
// in-degrees only (out-degrees counted in k_bin)
__global__ void k_degree(const int* __restrict__ dst, int E) {
    int e = blockIdx.x * blockDim.x + threadIdx.x;
    if (e < E) atomicAdd(&g_deg[NN + dst[e]], 1);
}

// --- 3-phase multi-block exclusive scan of degI -> rowptr ---
__global__ void k_scan1() {   // per-block sums
    __shared__ int ws[8];
    int i = blockIdx.x * 256 + threadIdx.x;
    int v = (i < NN) ? g_deg[NN + i] : 0;
#pragma unroll
    for (int o = 16; o > 0; o >>= 1) v += __shfl_down_sync(0xFFFFFFFFu, v, o);
    if ((threadIdx.x & 31) == 0) ws[threadIdx.x >> 5] = v;
    __syncthreads();
    if (threadIdx.x < 8) {
        int s = ws[threadIdx.x];
#pragma unroll
        for (int o = 4; o > 0; o >>= 1) s += __shfl_down_sync(0xFFu, s, o);
        if (threadIdx.x == 0) g_part[blockIdx.x] = s;
    }
}
__global__ void k_scan2() {   // scan SCAN_B partials (1 block)
    __shared__ int ws[8];
    int t = threadIdx.x, lane = t & 31, w = t >> 5;
    int v = (t < SCAN_B) ? g_part[t] : 0;
    int x = v;
#pragma unroll
    for (int o = 1; o < 32; o <<= 1) {
        int y = __shfl_up_sync(0xFFFFFFFFu, x, o);
        if (lane >= o) x += y;
    }
    if (lane == 31) ws[w] = x;
    __syncthreads();
    if (w == 0 && lane < 8) {
        int s = ws[lane];
#pragma unroll
        for (int o = 1; o < 8; o <<= 1) {
            int y = __shfl_up_sync(0xFFu, s, o);
            if (lane >= o) s += y;
        }
        ws[lane] = s;
    }
    __syncthreads();
    int woff = (w > 0) ? ws[w - 1] : 0;
    if (t < SCAN_B) g_poff[t] = x - v + woff;
}
__global__ void k_scan3() {   // rescan within block + offset -> rowptr (exclusive)
    __shared__ int ws[8];
    int t = threadIdx.x, lane = t & 31, w = t >> 5;
    int i = blockIdx.x * 256 + t;
    int v = (i < NN) ? g_deg[NN + i] : 0;
    int x = v;
#pragma unroll
    for (int o = 1; o < 32; o <<= 1) {
        int y = __shfl_up_sync(0xFFFFFFFFu, x, o);
        if (lane >= o) x += y;
    }
    if (lane == 31) ws[w] = x;
    __syncthreads();
    if (w == 0 && lane < 8) {
        int s = ws[lane];
#pragma unroll
        for (int o = 1; o < 8; o <<= 1) {
            int y = __shfl_up_sync(0xFFu, s, o);
            if (lane >= o) s += y;
        }
        ws[lane] = s;
    }
    __syncthreads();
    int woff = (w > 0) ? ws[w - 1] : 0;
    if (i < NN) g_rowptr[i] = x - v + woff + g_poff[blockIdx.x];
}

// bin edges into CSR-by-dst (bumps rowptr); also counts out-degrees (REDG)
__global__ void k_bin(const int* __restrict__ src, const int* __restrict__ dst,
                      const int* __restrict__ ef, int E) {
    int t = blockIdx.x * blockDim.x + threadIdx.x;
    int base = t * 2;
    if (base + 1 < E) {
        int2 s = *reinterpret_cast<const int2*>(src + base);
        int2 d = *reinterpret_cast<const int2*>(dst + base);
        int2 f = *reinterpret_cast<const int2*>(ef + base);
        atomicAdd(&g_deg[s.x], 1);
        atomicAdd(&g_deg[s.y], 1);
        int p0 = atomicAdd(&g_rowptr[d.x], 1);
        int p1 = atomicAdd(&g_rowptr[d.y], 1);
        g_csr[p0] = (unsigned)s.x | ((unsigned)(f.x & 1) << 31);
        g_csr[p1] = (unsigned)s.y | ((unsigned)(f.y & 1) << 31);
    } else if (base < E) {
        atomicAdd(&g_deg[src[base]], 1);
        int pos = atomicAdd(&g_rowptr[dst[base]], 1);
        g_csr[pos] = (unsigned)src[base] | ((unsigned)(ef[base] & 1) << 31);
    }
}

// hA = fp16(x * invO), invO inline from degO
__global__ void k_scale_x(const float4* __restrict__ x4) {
    int tid = blockIdx.x * blockDim.x + threadIdx.x;
    if (tid >= NN * DV4) return;
    int n = tid >> 4, c = tid & 15;
    float io = rsqrtf(fmaxf((float)g_deg[n], 1.0f));
    float4 v = x4[tid];
    v.x *= io; v.y *= io; v.z *= io; v.w *= io;
    store_h4(g_hA, (size_t)n, c, v);
}

// ---------------------------------------------------------------------------
// Pull aggregation (one warp/node, 16 lanes = 16 half4 cols, half-warps split edges)
// MODE 0: hB[d] = fp16( (sum hA[s]) * invI*invO )
// MODE 1: hY[d] = fp16( (sum hB[s]) * invI )
// MODE 2: out[d] = sum coef_e * hC[s]   (fp32)
template <int MODE>
__global__ void k_pull(float4* __restrict__ outbuf) {
    int gid = blockIdx.x * blockDim.x + threadIdx.x;
    int node = gid >> 5;
    if (node >= NN) return;
    int lane = gid & 31, col = lane & 15, half = lane >> 4;
    const __half* srcb = (MODE == 0) ? g_hA : (MODE == 1) ? g_hB : g_hC;
    int beg = node ? g_rowptr[node - 1] : 0;
    int end = g_rowptr[node];

    float4 acc = make_float4(0.f, 0.f, 0.f, 0.f);
    int j = beg + half;
    for (; j + 6 < end; j += 8) {
        unsigned v0 = g_csr[j], v1 = g_csr[j + 2], v2 = g_csr[j + 4], v3 = g_csr[j + 6];
        float c0 = 1.f, c1 = 1.f, c2 = 1.f, c3 = 1.f;
        if (MODE == 2) {
            c0 = (v0 >> 31) ? 1.f : 2.f; c1 = (v1 >> 31) ? 1.f : 2.f;
            c2 = (v2 >> 31) ? 1.f : 2.f; c3 = (v3 >> 31) ? 1.f : 2.f;
        }
        acc_h4(srcb, v0, col, c0, acc);
        acc_h4(srcb, v1, col, c1, acc);
        acc_h4(srcb, v2, col, c2, acc);
        acc_h4(srcb, v3, col, c3, acc);
    }
    for (; j < end; j += 2) {
        unsigned v = g_csr[j];
        float c = (MODE == 2) ? ((v >> 31) ? 1.f : 2.f) : 1.f;
        acc_h4(srcb, v, col, c, acc);
    }
    acc.x += __shfl_xor_sync(0xFFFFFFFFu, acc.x, 16);
    acc.y += __shfl_xor_sync(0xFFFFFFFFu, acc.y, 16);
    acc.z += __shfl_xor_sync(0xFFFFFFFFu, acc.z, 16);
    acc.w += __shfl_xor_sync(0xFFFFFFFFu, acc.w, 16);

    if (half == 0) {
        if (MODE == 0) {
            float sc = rsqrtf(fmaxf((float)g_deg[NN + node], 1.0f))
                     * rsqrtf(fmaxf((float)g_deg[node], 1.0f));
            acc.x *= sc; acc.y *= sc; acc.z *= sc; acc.w *= sc;
            store_h4(g_hB, (size_t)node, col, acc);
        } else if (MODE == 1) {
            float sc = rsqrtf(fmaxf((float)g_deg[NN + node], 1.0f));
            acc.x *= sc; acc.y *= sc; acc.z *= sc; acc.w *= sc;
            store_h4(g_hY, (size_t)node, col, acc);
        } else {
            outbuf[node * DV4 + col] = acc;
        }
    }
}

// hC = fp16( hY @ W + b ), grid-stride (W smem load amortized)
__global__ void k_gemm(const float* __restrict__ W, const float* __restrict__ b) {
    __shared__ float Ws[DD * DD];
    __shared__ float bs[DD];
    for (int i = threadIdx.x; i < DD * DD; i += blockDim.x) Ws[i] = W[i];
    if (threadIdx.x < DD) bs[threadIdx.x] = b[threadIdx.x];
    __syncthreads();

    for (int tid = blockIdx.x * blockDim.x + threadIdx.x; tid < NN * DV4;
         tid += gridDim.x * blockDim.x) {
        int n = tid >> 4;
        int jq = (tid & 15) * 4;
        const uint4* rowh = reinterpret_cast<const uint4*>(g_hY + (size_t)n * DD);

        uint64_t acc0 = pack2(bs[jq],     bs[jq + 1]);
        uint64_t acc1 = pack2(bs[jq + 2], bs[jq + 3]);
#pragma unroll
        for (int kb = 0; kb < 8; kb++) {          // 8 halves per uint4... (16B)
            uint4 r = rowh[kb];
            const __half2* hp = reinterpret_cast<const __half2*>(&r);
            float f[8];
#pragma unroll
            for (int q = 0; q < 4; q++) {
                float2 ff = __half22float2(hp[q]);
                f[2 * q] = ff.x; f[2 * q + 1] = ff.y;
            }
#pragma unroll
            for (int c = 0; c < 8; c++) {
                int k = kb * 8 + c;
                uint64_t x2 = pack2(f[c], f[c]);
                ulonglong2 w2 = *reinterpret_cast<const ulonglong2*>(Ws + k * DD + jq);
                fma2(acc0, x2, w2.x);
                fma2(acc1, x2, w2.y);
            }
        }
        float4 o;
        unpack2(acc0, o.x, o.y);
        unpack2(acc1, o.z, o.w);
        store_h4(g_hC, (size_t)n, (tid & 15), o);
    }
}

extern "C" void kernel_launch(void* const* d_in, const int* in_sizes, int n_in,
                              void* d_out, int out_size) {
    const float4* x4  = (const float4*)d_in[0];
    const float*  W   = (const float*)d_in[1];
    const float*  b   = (const float*)d_in[2];
    const int*    src = (const int*)d_in[3];
    const int*    dst = (const int*)d_in[4];
    const int*    ef  = (const int*)d_in[5];
    float4* out = (float4*)d_out;

    const int E = in_sizes[3];
    const int TB = 256;
    int gE    = (E + TB - 1) / TB;
    int gE2   = ((E + 1) / 2 + TB - 1) / TB;
    int gN16  = (NN * DV4 + TB - 1) / TB;
    int gWarp = (NN * 32 + TB - 1) / TB;

    void* degPtr = nullptr;
    cudaGetSymbolAddress(&degPtr, g_deg);
    cudaMemsetAsync(degPtr, 0, 2 * NN * sizeof(int));

    k_degree<<<gE, TB>>>(dst, E);
    k_scan1<<<SCAN_B, TB>>>();
    k_scan2<<<1, TB>>>();
    k_scan3<<<SCAN_B, TB>>>();
    k_bin<<<gE2, TB>>>(src, dst, ef, E);
    k_scale_x<<<gN16, TB>>>(x4);
    k_pull<0><<<gWarp, TB>>>(nullptr);
    k_pull<1><<<gWarp, TB>>>(nullptr);
    k_gemm<<<296, TB>>>(W, b);
    k_pull<2><<<gWarp, TB>>>(out);
}

// round 9
// speedup vs baseline: 1.5820x; 1.0188x over previous
#include <cuda_runtime.h>
#include <cuda_fp16.h>
#include <stdint.h>

#define NN 50000
#define DD 64
#define DV4 16
#define EMAX 800000
#define SCAN_B 196              // 196*256 = 50176 >= NN

// Scratch (device globals -- referenced ONLY inside device code)
__device__ __align__(256) __half g_hA[NN * DD];   // x * invO
__device__ __align__(256) __half g_hB[NN * DD];   // h1'
__device__ __align__(256) __half g_hY[NN * DD];   // invI * agg(h1')  (gemm input)
__device__ __align__(256) __half g_hC[NN * DD];   // h2 (post-gemm)
__device__ int g_deg[2 * NN];        // [0,NN)=degO, [NN,2NN)=degI
__device__ int g_rowptr[NN];         // excl prefix; becomes rowptr[d+1] after bin
__device__ int g_part[SCAN_B];
__device__ int g_poff[SCAN_B];
__device__ int g_scancnt;
__device__ unsigned g_csr[EMAX];     // src | (ef&1)<<31

__device__ __forceinline__ uint64_t pack2(float a, float b) {
    uint64_t r; asm("mov.b64 %0, {%1, %2};" : "=l"(r) : "f"(a), "f"(b)); return r;
}
__device__ __forceinline__ void unpack2(uint64_t v, float& a, float& b) {
    asm("mov.b64 {%0, %1}, %2;" : "=f"(a), "=f"(b) : "l"(v));
}
__device__ __forceinline__ void fma2(uint64_t& acc, uint64_t x, uint64_t w) {
    asm("fma.rn.f32x2 %0, %1, %2, %0;" : "+l"(acc) : "l"(x), "l"(w));
}
__device__ __forceinline__ void acc_h4(const __half* base, unsigned v, int col,
                                       float coef, float4& acc) {
    size_t s = (size_t)(v & 0x7FFFFFFFu);
    uint2 r = *reinterpret_cast<const uint2*>(base + s * DD + col * 4);
    float2 f0 = __half22float2(*reinterpret_cast<const __half2*>(&r.x));
    float2 f1 = __half22float2(*reinterpret_cast<const __half2*>(&r.y));
    acc.x += f0.x * coef; acc.y += f0.y * coef;
    acc.z += f1.x * coef; acc.w += f1.y * coef;
}
__device__ __forceinline__ void store_h4(__half* base, size_t n, int col, float4 v) {
    __half2 h0 = __floats2half2_rn(v.x, v.y);
    __half2 h1 = __floats2half2_rn(v.z, v.w);
    uint2 st;
    st.x = *reinterpret_cast<const unsigned*>(&h0);
    st.y = *reinterpret_cast<const unsigned*>(&h1);
    *reinterpret_cast<uint2*>(base + n * DD + col * 4) = st;
}

// ---------------------------------------------------------------------------
// chain A: in-degrees (also resets the scan ticket for this replay)
__global__ void k_degI(const int* __restrict__ dst, int E) {
    if (blockIdx.x == 0 && threadIdx.x == 0) g_scancnt = 0;
    int e = blockIdx.x * blockDim.x + threadIdx.x;
    if (e < E) atomicAdd(&g_deg[NN + dst[e]], 1);
}

// chain B: out-degrees (fire-and-forget)
__global__ void k_degO(const int* __restrict__ src, int E) {
    int e = blockIdx.x * blockDim.x + threadIdx.x;
    if (e < E) atomicAdd(&g_deg[src[e]], 1);
}

// scan phase 1+2 fused: block sums; last-done block scans the partials
__global__ void k_scan1() {
    __shared__ int ws[8];
    __shared__ int islast;
    int t = threadIdx.x, lane = t & 31, w = t >> 5;
    int i = blockIdx.x * 256 + t;
    int v = (i < NN) ? g_deg[NN + i] : 0;
    int s = v;
#pragma unroll
    for (int o = 16; o > 0; o >>= 1) s += __shfl_down_sync(0xFFFFFFFFu, s, o);
    if (lane == 0) ws[w] = s;
    __syncthreads();
    if (t == 0) {
        int tot = 0;
#pragma unroll
        for (int q = 0; q < 8; q++) tot += ws[q];
        g_part[blockIdx.x] = tot;
        __threadfence();
        int c = atomicAdd(&g_scancnt, 1);
        islast = (c == SCAN_B - 1);
    }
    __syncthreads();
    if (islast) {
        __threadfence();
        int pv = (t < SCAN_B) ? *(volatile int*)(g_part + t) : 0;
        int x = pv;
#pragma unroll
        for (int o = 1; o < 32; o <<= 1) {
            int y = __shfl_up_sync(0xFFFFFFFFu, x, o);
            if (lane >= o) x += y;
        }
        if (lane == 31) ws[w] = x;
        __syncthreads();
        if (w == 0 && lane < 8) {
            int ss = ws[lane];
#pragma unroll
            for (int o = 1; o < 8; o <<= 1) {
                int y = __shfl_up_sync(0xFFu, ss, o);
                if (lane >= o) ss += y;
            }
            ws[lane] = ss;
        }
        __syncthreads();
        int woff = (w > 0) ? ws[w - 1] : 0;
        if (t < SCAN_B) g_poff[t] = x - pv + woff;
    }
}

// scan phase 3: rescan within block + offset -> rowptr (exclusive)
__global__ void k_scan3() {
    __shared__ int ws[8];
    int t = threadIdx.x, lane = t & 31, w = t >> 5;
    int i = blockIdx.x * 256 + t;
    int v = (i < NN) ? g_deg[NN + i] : 0;
    int x = v;
#pragma unroll
    for (int o = 1; o < 32; o <<= 1) {
        int y = __shfl_up_sync(0xFFFFFFFFu, x, o);
        if (lane >= o) x += y;
    }
    if (lane == 31) ws[w] = x;
    __syncthreads();
    if (w == 0 && lane < 8) {
        int s = ws[lane];
#pragma unroll
        for (int o = 1; o < 8; o <<= 1) {
            int y = __shfl_up_sync(0xFFu, s, o);
            if (lane >= o) s += y;
        }
        ws[lane] = s;
    }
    __syncthreads();
    int woff = (w > 0) ? ws[w - 1] : 0;
    if (i < NN) g_rowptr[i] = x - v + woff + g_poff[blockIdx.x];
}

// bin edges into CSR-by-dst (bumps rowptr in place; 2 edges/thread)
__global__ void k_bin(const int* __restrict__ src, const int* __restrict__ dst,
                      const int* __restrict__ ef, int E) {
    int t = blockIdx.x * blockDim.x + threadIdx.x;
    int base = t * 2;
    if (base + 1 < E) {
        int2 s = *reinterpret_cast<const int2*>(src + base);
        int2 d = *reinterpret_cast<const int2*>(dst + base);
        int2 f = *reinterpret_cast<const int2*>(ef + base);
        int p0 = atomicAdd(&g_rowptr[d.x], 1);
        int p1 = atomicAdd(&g_rowptr[d.y], 1);
        g_csr[p0] = (unsigned)s.x | ((unsigned)(f.x & 1) << 31);
        g_csr[p1] = (unsigned)s.y | ((unsigned)(f.y & 1) << 31);
    } else if (base < E) {
        int pos = atomicAdd(&g_rowptr[dst[base]], 1);
        g_csr[pos] = (unsigned)src[base] | ((unsigned)(ef[base] & 1) << 31);
    }
}

// chain B: hA = fp16(x * invO)
__global__ void k_scale_x(const float4* __restrict__ x4) {
    int tid = blockIdx.x * blockDim.x + threadIdx.x;
    if (tid >= NN * DV4) return;
    int n = tid >> 4, c = tid & 15;
    float io = rsqrtf(fmaxf((float)g_deg[n], 1.0f));
    float4 v = x4[tid];
    v.x *= io; v.y *= io; v.z *= io; v.w *= io;
    store_h4(g_hA, (size_t)n, c, v);
}

// ---------------------------------------------------------------------------
// Pull aggregation (one warp/node, 16 lanes = 16 half4 cols, half-warps split edges)
// MODE 0: hB[d] = fp16( (sum hA[s]) * invI*invO )
// MODE 1: hY[d] = fp16( (sum hB[s]) * invI )
// MODE 2: out[d] = sum coef_e * hC[s]   (fp32)
template <int MODE>
__global__ void k_pull(float4* __restrict__ outbuf) {
    int gid = blockIdx.x * blockDim.x + threadIdx.x;
    int node = gid >> 5;
    if (node >= NN) return;
    int lane = gid & 31, col = lane & 15, half = lane >> 4;
    const __half* srcb = (MODE == 0) ? g_hA : (MODE == 1) ? g_hB : g_hC;
    int beg = node ? g_rowptr[node - 1] : 0;
    int end = g_rowptr[node];

    float4 acc = make_float4(0.f, 0.f, 0.f, 0.f);
    int j = beg + half;
    for (; j + 6 < end; j += 8) {
        unsigned v0 = g_csr[j], v1 = g_csr[j + 2], v2 = g_csr[j + 4], v3 = g_csr[j + 6];
        float c0 = 1.f, c1 = 1.f, c2 = 1.f, c3 = 1.f;
        if (MODE == 2) {
            c0 = (v0 >> 31) ? 1.f : 2.f; c1 = (v1 >> 31) ? 1.f : 2.f;
            c2 = (v2 >> 31) ? 1.f : 2.f; c3 = (v3 >> 31) ? 1.f : 2.f;
        }
        acc_h4(srcb, v0, col, c0, acc);
        acc_h4(srcb, v1, col, c1, acc);
        acc_h4(srcb, v2, col, c2, acc);
        acc_h4(srcb, v3, col, c3, acc);
    }
    for (; j < end; j += 2) {
        unsigned v = g_csr[j];
        float c = (MODE == 2) ? ((v >> 31) ? 1.f : 2.f) : 1.f;
        acc_h4(srcb, v, col, c, acc);
    }
    acc.x += __shfl_xor_sync(0xFFFFFFFFu, acc.x, 16);
    acc.y += __shfl_xor_sync(0xFFFFFFFFu, acc.y, 16);
    acc.z += __shfl_xor_sync(0xFFFFFFFFu, acc.z, 16);
    acc.w += __shfl_xor_sync(0xFFFFFFFFu, acc.w, 16);

    if (half == 0) {
        if (MODE == 0) {
            float sc = rsqrtf(fmaxf((float)g_deg[NN + node], 1.0f))
                     * rsqrtf(fmaxf((float)g_deg[node], 1.0f));
            acc.x *= sc; acc.y *= sc; acc.z *= sc; acc.w *= sc;
            store_h4(g_hB, (size_t)node, col, acc);
        } else if (MODE == 1) {
            float sc = rsqrtf(fmaxf((float)g_deg[NN + node], 1.0f));
            acc.x *= sc; acc.y *= sc; acc.z *= sc; acc.w *= sc;
            store_h4(g_hY, (size_t)node, col, acc);
        } else {
            outbuf[node * DV4 + col] = acc;
        }
    }
}

// hC = fp16( hY @ W + b ), grid-stride
__global__ void k_gemm(const float* __restrict__ W, const float* __restrict__ b) {
    __shared__ float Ws[DD * DD];
    __shared__ float bs[DD];
    for (int i = threadIdx.x; i < DD * DD; i += blockDim.x) Ws[i] = W[i];
    if (threadIdx.x < DD) bs[threadIdx.x] = b[threadIdx.x];
    __syncthreads();

    for (int tid = blockIdx.x * blockDim.x + threadIdx.x; tid < NN * DV4;
         tid += gridDim.x * blockDim.x) {
        int n = tid >> 4;
        int jq = (tid & 15) * 4;
        const uint4* rowh = reinterpret_cast<const uint4*>(g_hY + (size_t)n * DD);

        uint64_t acc0 = pack2(bs[jq],     bs[jq + 1]);
        uint64_t acc1 = pack2(bs[jq + 2], bs[jq + 3]);
#pragma unroll
        for (int kb = 0; kb < 8; kb++) {
            uint4 r = rowh[kb];
            const __half2* hp = reinterpret_cast<const __half2*>(&r);
            float f[8];
#pragma unroll
            for (int q = 0; q < 4; q++) {
                float2 ff = __half22float2(hp[q]);
                f[2 * q] = ff.x; f[2 * q + 1] = ff.y;
            }
#pragma unroll
            for (int c = 0; c < 8; c++) {
                int k = kb * 8 + c;
                uint64_t x2 = pack2(f[c], f[c]);
                ulonglong2 w2 = *reinterpret_cast<const ulonglong2*>(Ws + k * DD + jq);
                fma2(acc0, x2, w2.x);
                fma2(acc1, x2, w2.y);
            }
        }
        float4 o;
        unpack2(acc0, o.x, o.y);
        unpack2(acc1, o.z, o.w);
        store_h4(g_hC, (size_t)n, (tid & 15), o);
    }
}

extern "C" void kernel_launch(void* const* d_in, const int* in_sizes, int n_in,
                              void* d_out, int out_size) {
    const float4* x4  = (const float4*)d_in[0];
    const float*  W   = (const float*)d_in[1];
    const float*  b   = (const float*)d_in[2];
    const int*    src = (const int*)d_in[3];
    const int*    dst = (const int*)d_in[4];
    const int*    ef  = (const int*)d_in[5];
    float4* out = (float4*)d_out;

    const int E = in_sizes[3];
    const int TB = 256;
    int gE    = (E + TB - 1) / TB;
    int gE2   = ((E + 1) / 2 + TB - 1) / TB;
    int gN16  = (NN * DV4 + TB - 1) / TB;
    int gWarp = (NN * 32 + TB - 1) / TB;

    // side stream + events for fork/join (host objects only; no device memory)
    static cudaStream_t s2 = nullptr;
    static cudaEvent_t evFork = nullptr, evJoin = nullptr;
    if (!s2) {
        cudaStreamCreateWithFlags(&s2, cudaStreamNonBlocking);
        cudaEventCreateWithFlags(&evFork, cudaEventDisableTiming);
        cudaEventCreateWithFlags(&evJoin, cudaEventDisableTiming);
    }

    void* degPtr = nullptr;
    cudaGetSymbolAddress(&degPtr, g_deg);
    cudaMemsetAsync(degPtr, 0, 2 * NN * sizeof(int));

    // fork: chain B (degO -> scale_x) on s2, concurrent with chain A
    cudaEventRecord(evFork, 0);
    cudaStreamWaitEvent(s2, evFork, 0);
    k_degO<<<gE, TB, 0, s2>>>(src, E);
    k_scale_x<<<gN16, TB, 0, s2>>>(x4);
    cudaEventRecord(evJoin, s2);

    // chain A (critical path)
    k_degI<<<gE, TB>>>(dst, E);
    k_scan1<<<SCAN_B, TB>>>();
    k_scan3<<<SCAN_B, TB>>>();
    k_bin<<<gE2, TB>>>(src, dst, ef, E);

    // join before first pull (needs hA + csr)
    cudaStreamWaitEvent((cudaStream_t)0, evJoin, 0);

    k_pull<0><<<gWarp, TB>>>(nullptr);
    k_pull<1><<<gWarp, TB>>>(nullptr);
    k_gemm<<<296, TB>>>(W, b);
    k_pull<2><<<gWarp, TB>>>(out);
}